// round 6
// baseline (speedup 1.0000x reference)
#include <cuda_runtime.h>
#include <cuda_bf16.h>
#include <cstdint>
#include <math.h>

// Problem constants
#define Bn 8
#define Cn 256
#define Nn 4096   // 64*64

// ---------------------------------------------------------------------------
// Scratch (device globals; no allocation allowed)
// ---------------------------------------------------------------------------
__device__ __nv_bfloat16 g_qh[(size_t)Bn * Nn * Cn];   // q hi  [B, N, C]
__device__ __nv_bfloat16 g_ql[(size_t)Bn * Nn * Cn];   // q lo
__device__ __nv_bfloat16 g_kh[(size_t)Bn * Nn * Cn];   // k hi  [B, N, C]
__device__ __nv_bfloat16 g_kl[(size_t)Bn * Nn * Cn];   // k lo
__device__ __nv_bfloat16 g_vh[(size_t)Bn * Cn * Nn];   // v hi  [B, C, N]
__device__ __nv_bfloat16 g_vl[(size_t)Bn * Cn * Nn];   // v lo
__device__ float         g_S [(size_t)Bn * Nn * Nn];   // scores fp32
__device__ __nv_bfloat16 g_Ph[(size_t)Bn * Nn * Nn];   // softmax hi [B, N, N]
__device__ __nv_bfloat16 g_Pl[(size_t)Bn * Nn * Nn];   // softmax lo

// ---------------------------------------------------------------------------
// Helpers
// ---------------------------------------------------------------------------
__device__ __forceinline__ uint32_t smem_u32(const void* p) {
    uint32_t a;
    asm("{ .reg .u64 t; cvta.to.shared.u64 t, %1; cvt.u32.u64 %0, t; }"
        : "=r"(a) : "l"(p));
    return a;
}

// SW64 swizzle for 64-byte rows: bits[5:4] ^= bits[8:7]
#define SMEM_SWIZZLE_64B(off) ((off) ^ (((off) >> 3) & 0x30))

__device__ __forceinline__ void ldmx4(uint32_t* r, uint32_t a) {
    asm volatile("ldmatrix.sync.aligned.m8n8.x4.shared.b16 {%0,%1,%2,%3}, [%4];"
        : "=r"(r[0]), "=r"(r[1]), "=r"(r[2]), "=r"(r[3]) : "r"(a));
}

__device__ __forceinline__ void mma16816(float* d, const uint32_t* a,
                                         uint32_t b0, uint32_t b1) {
    asm volatile(
        "mma.sync.aligned.m16n8k16.row.col.f32.bf16.bf16.f32 "
        "{%0,%1,%2,%3}, {%4,%5,%6,%7}, {%8,%9}, {%0,%1,%2,%3};"
        : "+f"(d[0]), "+f"(d[1]), "+f"(d[2]), "+f"(d[3])
        : "r"(a[0]), "r"(a[1]), "r"(a[2]), "r"(a[3]), "r"(b0), "r"(b1));
}

// Copy one 128-row x 32-bf16 tile (64B rows, SW64 swizzle) via cp.async.
// 128 threads -> 4 transfers of 16B each.
__device__ __forceinline__ void cp_tile(uint32_t sdst, const __nv_bfloat16* g,
                                        int rs, int tid) {
    #pragma unroll
    for (int t = 0; t < 4; t++) {
        int u = tid + t * 128;          // 0..511 16B transfers
        int row = u >> 2, q = u & 3;
        uint32_t d = sdst + SMEM_SWIZZLE_64B((uint32_t)(row * 64 + q * 16));
        const void* s = g + (size_t)row * rs + q * 8;
        asm volatile("cp.async.cg.shared.global [%0], [%1], 16;"
                     :: "r"(d), "l"(s));
    }
}

#define CP_COMMIT() asm volatile("cp.async.commit_group;" ::: "memory")
#define CP_WAIT2()  asm volatile("cp.async.wait_group 2;" ::: "memory")
#define CP_WAIT1()  asm volatile("cp.async.wait_group 1;" ::: "memory")
#define CP_WAIT0()  asm volatile("cp.async.wait_group 0;" ::: "memory")

// SMEM: 3 stages x 4 tiles (Ah, Al, Bh, Bl) x 8KB = 96KB
#define TILE_B   8192
#define STAGE_B  (4 * TILE_B)
#define NSTAGES  3
#define MMA_SMEM (NSTAGES * STAGE_B)

// ---------------------------------------------------------------------------
// HMMA mainloop: acc[4][8][4] += A(128xK) @ B(128xK)^T, 2-way bf16 split
// (Ah*Bh + Ah*Bl + Al*Bh).  K in chunks of 32.
// 4 warps: warp tile = 64(i) x 64(j); iBase=(wid>>1)*64, jBase=(wid&1)*64.
// ---------------------------------------------------------------------------
__device__ __forceinline__ void mma_mainloop(
    uint32_t sbase,
    const __nv_bfloat16* Ah, const __nv_bfloat16* Al,
    const __nv_bfloat16* Bh, const __nv_bfloat16* Bl,
    int rsA, int rsB, int nch,
    float acc[4][8][4], int tid, int wid, int lane)
{
    const int iBase = (wid >> 1) * 64;
    const int jBase = (wid & 1) * 64;
    const uint32_t lsw  = (uint32_t)(((lane >> 1) & 3) * 16);
    const uint32_t aoff = (uint32_t)((iBase + (lane & 15)) * 64 + (lane >> 4) * 16);
    const uint32_t boff = (uint32_t)((jBase + (lane & 15)) * 64 + (lane >> 4) * 16);

    // Prefetch chunks 0 and 1
    #pragma unroll
    for (int p = 0; p < 2; p++) {
        uint32_t st = sbase + p * STAGE_B;
        int ko = p * 32;
        cp_tile(st + 0 * TILE_B, Ah + ko, rsA, tid);
        cp_tile(st + 1 * TILE_B, Al + ko, rsA, tid);
        cp_tile(st + 2 * TILE_B, Bh + ko, rsB, tid);
        cp_tile(st + 3 * TILE_B, Bl + ko, rsB, tid);
        CP_COMMIT();
    }

    int stage = 0;
    #pragma unroll 1
    for (int c = 0; c < nch; c++) {
        if (c + 2 < nch) {
            int ps = stage + 2; if (ps >= NSTAGES) ps -= NSTAGES;
            uint32_t st = sbase + ps * STAGE_B;
            int ko = (c + 2) * 32;
            cp_tile(st + 0 * TILE_B, Ah + ko, rsA, tid);
            cp_tile(st + 1 * TILE_B, Al + ko, rsA, tid);
            cp_tile(st + 2 * TILE_B, Bh + ko, rsB, tid);
            cp_tile(st + 3 * TILE_B, Bl + ko, rsB, tid);
            CP_COMMIT();
            CP_WAIT2();
        } else if (c + 2 == nch) {
            CP_WAIT1();
        } else {
            CP_WAIT0();
        }
        __syncthreads();

        uint32_t tb = sbase + stage * STAGE_B;
        #pragma unroll
        for (int ks = 0; ks < 2; ks++) {
            uint32_t kb = (uint32_t)(ks * 32);

            uint32_t ah[4][4], al[4][4];
            #pragma unroll
            for (int it = 0; it < 4; it++) {
                uint32_t o = (aoff + it * 1024 + kb) ^ lsw;
                ldmx4(ah[it], tb + o);
                ldmx4(al[it], tb + TILE_B + o);
            }
            uint32_t bh[8][2], bl[8][2];
            #pragma unroll
            for (int jp = 0; jp < 4; jp++) {
                uint32_t o = (boff + jp * 1024 + kb) ^ lsw;
                uint32_t t4[4];
                ldmx4(t4, tb + 2 * TILE_B + o);
                bh[jp * 2][0]     = t4[0]; bh[jp * 2][1]     = t4[2];
                bh[jp * 2 + 1][0] = t4[1]; bh[jp * 2 + 1][1] = t4[3];
                ldmx4(t4, tb + 3 * TILE_B + o);
                bl[jp * 2][0]     = t4[0]; bl[jp * 2][1]     = t4[2];
                bl[jp * 2 + 1][0] = t4[1]; bl[jp * 2 + 1][1] = t4[3];
            }

            #pragma unroll
            for (int it = 0; it < 4; it++)
                #pragma unroll
                for (int nt = 0; nt < 8; nt++) {
                    mma16816(acc[it][nt], ah[it], bh[nt][0], bh[nt][1]);
                    mma16816(acc[it][nt], ah[it], bl[nt][0], bl[nt][1]);
                    mma16816(acc[it][nt], al[it], bh[nt][0], bh[nt][1]);
                }
        }
        __syncthreads();

        if (++stage == NSTAGES) stage = 0;
    }
}

// ---------------------------------------------------------------------------
// Kernel 1: 1x1 conv projection (SIMT fp32) -> bf16 hi/lo split outputs.
// vmode=0: out [N, C] (q, k).  vmode=1: out [C, N] (v).
// ---------------------------------------------------------------------------
__device__ __forceinline__ void store8_bf16_split(__nv_bfloat16* dh,
                                                  __nv_bfloat16* dl,
                                                  const float* f) {
    uint4 uh, ul;
    __nv_bfloat162* ph = reinterpret_cast<__nv_bfloat162*>(&uh);
    __nv_bfloat162* pl = reinterpret_cast<__nv_bfloat162*>(&ul);
    #pragma unroll
    for (int k = 0; k < 4; k++) {
        float a = f[2 * k], b = f[2 * k + 1];
        __nv_bfloat16 ah = __float2bfloat16_rn(a);
        __nv_bfloat16 bh = __float2bfloat16_rn(b);
        float al = a - __bfloat162float(ah);
        float bl = b - __bfloat162float(bh);
        ph[k] = __halves2bfloat162(ah, bh);
        pl[k] = __halves2bfloat162(__float2bfloat16_rn(al), __float2bfloat16_rn(bl));
    }
    *reinterpret_cast<uint4*>(dh) = uh;
    *reinterpret_cast<uint4*>(dl) = ul;
}

__global__ void __launch_bounds__(256, 2)
proj_kernel(const float* __restrict__ x,
            const float* __restrict__ W,
            const float* __restrict__ bias,
            __nv_bfloat16* __restrict__ oh,
            __nv_bfloat16* __restrict__ ol,
            int vmode) {
    __shared__ __align__(16) float As[16][128];   // As[cc][nn]
    __shared__ __align__(16) float Bs[16][132];   // Bs[cc][oo]

    const int b  = blockIdx.z;
    const int o0 = blockIdx.y * 128;
    const int n0 = blockIdx.x * 128;
    const int tid = threadIdx.x;
    const int tx = tid & 15, ty = tid >> 4;

    const float* xb = x + (size_t)b * Cn * Nn;

    float acc[8][8] = {};

    for (int c0 = 0; c0 < Cn; c0 += 16) {
        #pragma unroll
        for (int k = 0; k < 2; k++) {
            int p = tid + k * 256;
            int cc = p >> 5, nn4 = (p & 31) * 4;
            *reinterpret_cast<float4*>(&As[cc][nn4]) =
                *reinterpret_cast<const float4*>(&xb[(size_t)(c0 + cc) * Nn + n0 + nn4]);
        }
        #pragma unroll
        for (int k = 0; k < 2; k++) {
            int p = tid + k * 256;
            int oo = p >> 2, c4 = (p & 3) * 4;
            float4 w = *reinterpret_cast<const float4*>(&W[(size_t)(o0 + oo) * Cn + c0 + c4]);
            Bs[c4 + 0][oo] = w.x;
            Bs[c4 + 1][oo] = w.y;
            Bs[c4 + 2][oo] = w.z;
            Bs[c4 + 3][oo] = w.w;
        }
        __syncthreads();

        #pragma unroll
        for (int cc = 0; cc < 16; cc++) {
            float4 a0 = *reinterpret_cast<const float4*>(&As[cc][ty * 8]);
            float4 a1 = *reinterpret_cast<const float4*>(&As[cc][ty * 8 + 4]);
            float4 b0 = *reinterpret_cast<const float4*>(&Bs[cc][tx * 8]);
            float4 b1 = *reinterpret_cast<const float4*>(&Bs[cc][tx * 8 + 4]);
            float a[8] = {a0.x, a0.y, a0.z, a0.w, a1.x, a1.y, a1.z, a1.w};
            float bb[8] = {b0.x, b0.y, b0.z, b0.w, b1.x, b1.y, b1.z, b1.w};
            #pragma unroll
            for (int i = 0; i < 8; i++)
                #pragma unroll
                for (int j = 0; j < 8; j++)
                    acc[i][j] += a[i] * bb[j];
        }
        __syncthreads();
    }

    float bj[8];
    #pragma unroll
    for (int j = 0; j < 8; j++) bj[j] = bias[o0 + tx * 8 + j];

    if (!vmode) {
        __nv_bfloat16* dh = oh + (size_t)b * Nn * Cn;
        __nv_bfloat16* dl = ol + (size_t)b * Nn * Cn;
        #pragma unroll
        for (int i = 0; i < 8; i++) {
            float f[8];
            #pragma unroll
            for (int j = 0; j < 8; j++) f[j] = acc[i][j] + bj[j];
            size_t base = (size_t)(n0 + ty * 8 + i) * Cn + o0 + tx * 8;
            store8_bf16_split(dh + base, dl + base, f);
        }
    } else {
        __nv_bfloat16* dh = oh + (size_t)b * Cn * Nn;
        __nv_bfloat16* dl = ol + (size_t)b * Cn * Nn;
        #pragma unroll
        for (int j = 0; j < 8; j++) {
            float f[8];
            #pragma unroll
            for (int i = 0; i < 8; i++) f[i] = acc[i][j] + bj[j];
            size_t base = (size_t)(o0 + tx * 8 + j) * Nn + n0 + ty * 8;
            store8_bf16_split(dh + base, dl + base, f);
        }
    }
}

// ---------------------------------------------------------------------------
// Kernel 2: scores via HMMA.  S[b,i,j] = mask[b,i] * <q_i, k_j>
// ---------------------------------------------------------------------------
__global__ void __launch_bounds__(128, 2)
scores_mma(const float* __restrict__ mask) {
    extern __shared__ char smem[];
    uint32_t sbase = smem_u32(smem);
    const int tid = threadIdx.x;
    const int wid = tid >> 5, lane = tid & 31;

    const int b  = blockIdx.z;
    const int i0 = blockIdx.y * 128;
    const int j0 = blockIdx.x * 128;

    const __nv_bfloat16* Ah = g_qh + ((size_t)b * Nn + i0) * Cn;
    const __nv_bfloat16* Al = g_ql + ((size_t)b * Nn + i0) * Cn;
    const __nv_bfloat16* Bh = g_kh + ((size_t)b * Nn + j0) * Cn;
    const __nv_bfloat16* Bl = g_kl + ((size_t)b * Nn + j0) * Cn;

    float acc[4][8][4] = {};
    mma_mainloop(sbase, Ah, Al, Bh, Bl, Cn, Cn, Cn / 32, acc, tid, wid, lane);

    // Epilogue: warp tile 64(i) x 64(j)
    const int iBase = (wid >> 1) * 64;
    const int jBase = (wid & 1) * 64;
    const int g = lane >> 2, cp2 = (lane & 3) * 2;
    const float* mb = mask + (size_t)b * Nn;
    float* Sb = g_S + (size_t)b * Nn * Nn;

    #pragma unroll
    for (int it = 0; it < 4; it++) {
        int r1 = i0 + iBase + it * 16 + g;
        float m1 = mb[r1], m2 = mb[r1 + 8];
        #pragma unroll
        for (int nt = 0; nt < 8; nt++) {
            int cc = j0 + jBase + nt * 8 + cp2;
            float2 v1 = {acc[it][nt][0] * m1, acc[it][nt][1] * m1};
            float2 v2 = {acc[it][nt][2] * m2, acc[it][nt][3] * m2};
            *reinterpret_cast<float2*>(&Sb[(size_t)r1 * Nn + cc])       = v1;
            *reinterpret_cast<float2*>(&Sb[(size_t)(r1 + 8) * Nn + cc]) = v2;
        }
    }
}

// ---------------------------------------------------------------------------
// Kernel 3: row softmax over S; writes P as bf16 hi/lo.
// ---------------------------------------------------------------------------
__global__ void softmax_kernel() {
    const size_t row = blockIdx.x;
    const float* src = g_S + row * Nn;
    __nv_bfloat16* dh = g_Ph + row * Nn;
    __nv_bfloat16* dl = g_Pl + row * Nn;

    const int tid  = threadIdx.x;
    const int warp = tid >> 5;
    const int lane = tid & 31;

    __shared__ float sred[8];
    __shared__ float sbcast;

    float2 v[8];
    float mx = -1e30f;
    #pragma unroll
    for (int t = 0; t < 8; t++) {
        v[t] = *reinterpret_cast<const float2*>(&src[t * 512 + tid * 2]);
        mx = fmaxf(mx, fmaxf(v[t].x, v[t].y));
    }
    #pragma unroll
    for (int o = 16; o > 0; o >>= 1)
        mx = fmaxf(mx, __shfl_xor_sync(0xffffffffu, mx, o));
    if (lane == 0) sred[warp] = mx;
    __syncthreads();
    if (warp == 0) {
        float x = sred[lane & 7];
        #pragma unroll
        for (int o = 4; o > 0; o >>= 1)
            x = fmaxf(x, __shfl_xor_sync(0xffffffffu, x, o));
        if (lane == 0) sbcast = x;
    }
    __syncthreads();
    mx = sbcast;

    float s = 0.f;
    #pragma unroll
    for (int t = 0; t < 8; t++) {
        v[t].x = __expf(v[t].x - mx);
        v[t].y = __expf(v[t].y - mx);
        s += v[t].x + v[t].y;
    }
    #pragma unroll
    for (int o = 16; o > 0; o >>= 1)
        s += __shfl_xor_sync(0xffffffffu, s, o);
    __syncthreads();
    if (lane == 0) sred[warp] = s;
    __syncthreads();
    if (warp == 0) {
        float x = sred[lane & 7];
        #pragma unroll
        for (int o = 4; o > 0; o >>= 1)
            x += __shfl_xor_sync(0xffffffffu, x, o);
        if (lane == 0) sbcast = x;
    }
    __syncthreads();
    const float inv = 1.f / sbcast;

    #pragma unroll
    for (int t = 0; t < 8; t++) {
        float a = v[t].x * inv, b = v[t].y * inv;
        __nv_bfloat16 ah = __float2bfloat16_rn(a);
        __nv_bfloat16 bh = __float2bfloat16_rn(b);
        float al = a - __bfloat162float(ah);
        float bl = b - __bfloat162float(bh);
        int off = t * 512 + tid * 2;
        *reinterpret_cast<__nv_bfloat162*>(&dh[off]) = __halves2bfloat162(ah, bh);
        *reinterpret_cast<__nv_bfloat162*>(&dl[off]) =
            __halves2bfloat162(__float2bfloat16_rn(al), __float2bfloat16_rn(bl));
    }
}

// ---------------------------------------------------------------------------
// Kernel 4: PV via HMMA (computes D^T: rows = c, cols = q) + final blend.
// D[c][q] = sum_j v[c][j] * P[q][j];  out[b,c,q] = queries*m + (1-m)*D
// ---------------------------------------------------------------------------
__global__ void __launch_bounds__(128, 2)
pv_mma(const float* __restrict__ mask,
       const float* __restrict__ queries,
       float* __restrict__ out) {
    extern __shared__ char smem[];
    uint32_t sbase = smem_u32(smem);
    const int tid = threadIdx.x;
    const int wid = tid >> 5, lane = tid & 31;

    const int b  = blockIdx.z;
    const int c0 = blockIdx.y * 128;
    const int q0 = blockIdx.x * 128;

    const __nv_bfloat16* Ah = g_vh + ((size_t)b * Cn + c0) * Nn;
    const __nv_bfloat16* Al = g_vl + ((size_t)b * Cn + c0) * Nn;
    const __nv_bfloat16* Bh = g_Ph + ((size_t)b * Nn + q0) * Nn;
    const __nv_bfloat16* Bl = g_Pl + ((size_t)b * Nn + q0) * Nn;

    float acc[4][8][4] = {};
    mma_mainloop(sbase, Ah, Al, Bh, Bl, Nn, Nn, Nn / 32, acc, tid, wid, lane);

    // Epilogue: rows = c, cols = q (contiguous in output)
    const int iBase = (wid >> 1) * 64;
    const int jBase = (wid & 1) * 64;
    const int g = lane >> 2, cp2 = (lane & 3) * 2;
    const float* mb = mask + (size_t)b * Nn;

    int   qc[8];
    float m0[8], m1[8];
    #pragma unroll
    for (int nt = 0; nt < 8; nt++) {
        qc[nt] = q0 + jBase + nt * 8 + cp2;
        m0[nt] = mb[qc[nt]];
        m1[nt] = mb[qc[nt] + 1];
    }

    #pragma unroll
    for (int it = 0; it < 4; it++) {
        int cr = c0 + iBase + it * 16 + g;
        #pragma unroll
        for (int nt = 0; nt < 8; nt++) {
            size_t gi1 = ((size_t)b * Cn + cr) * Nn + qc[nt];
            size_t gi2 = gi1 + (size_t)8 * Nn;
            float2 qa = *reinterpret_cast<const float2*>(&queries[gi1]);
            float2 qb = *reinterpret_cast<const float2*>(&queries[gi2]);
            float2 o1, o2;
            o1.x = qa.x * m0[nt] + (1.f - m0[nt]) * acc[it][nt][0];
            o1.y = qa.y * m1[nt] + (1.f - m1[nt]) * acc[it][nt][1];
            o2.x = qb.x * m0[nt] + (1.f - m0[nt]) * acc[it][nt][2];
            o2.y = qb.y * m1[nt] + (1.f - m1[nt]) * acc[it][nt][3];
            *reinterpret_cast<float2*>(&out[gi1]) = o1;
            *reinterpret_cast<float2*>(&out[gi2]) = o2;
        }
    }
}

// ---------------------------------------------------------------------------
// Launch
// ---------------------------------------------------------------------------
extern "C" void kernel_launch(void* const* d_in, const int* in_sizes, int n_in,
                              void* d_out, int out_size) {
    const float* queries = (const float*)d_in[0];
    const float* keys    = (const float*)d_in[1];
    const float* mask    = (const float*)d_in[2];
    const float* Wq      = (const float*)d_in[3];
    const float* bq      = (const float*)d_in[4];
    const float* Wk      = (const float*)d_in[5];
    const float* bk      = (const float*)d_in[6];
    const float* Wv      = (const float*)d_in[7];
    const float* bv      = (const float*)d_in[8];
    float* out = (float*)d_out;

    cudaFuncSetAttribute(scores_mma, cudaFuncAttributeMaxDynamicSharedMemorySize,
                         MMA_SMEM);
    cudaFuncSetAttribute(pv_mma, cudaFuncAttributeMaxDynamicSharedMemorySize,
                         MMA_SMEM);

    __nv_bfloat16 *qh, *ql, *kh, *kl, *vh, *vl;
    cudaGetSymbolAddress((void**)&qh, g_qh);
    cudaGetSymbolAddress((void**)&ql, g_ql);
    cudaGetSymbolAddress((void**)&kh, g_kh);
    cudaGetSymbolAddress((void**)&kl, g_kl);
    cudaGetSymbolAddress((void**)&vh, g_vh);
    cudaGetSymbolAddress((void**)&vl, g_vl);

    // Projections (SIMT fp32 -> bf16 hi/lo split outputs)
    dim3 gproj(Nn / 128, Cn / 128, Bn);
    proj_kernel<<<gproj, 256>>>(queries, Wq, bq, qh, ql, 0);
    proj_kernel<<<gproj, 256>>>(keys,    Wk, bk, kh, kl, 0);
    proj_kernel<<<gproj, 256>>>(keys,    Wv, bv, vh, vl, 1);

    // Scores (HMMA, 3-product bf16 split) + mask
    dim3 gsc(Nn / 128, Nn / 128, Bn);
    scores_mma<<<gsc, 128, MMA_SMEM>>>(mask);

    // Row softmax -> P hi/lo
    softmax_kernel<<<Bn * Nn, 256>>>();

    // PV (HMMA, computes D^T) + final blend
    dim3 gpv(Nn / 128, Cn / 128, Bn);
    pv_mma<<<gpv, 128, MMA_SMEM>>>(mask, queries, out);
}

// round 7
// speedup vs baseline: 1.0035x; 1.0035x over previous
#include <cuda_runtime.h>
#include <cuda_bf16.h>
#include <cstdint>
#include <math.h>

// Problem constants
#define Bn 8
#define Cn 256
#define Nn 4096   // 64*64

// ---------------------------------------------------------------------------
// Scratch (device globals; no allocation allowed)
// ---------------------------------------------------------------------------
__device__ __nv_bfloat16 g_qh[(size_t)Bn * Nn * Cn];   // q hi  [B, N, C]
__device__ __nv_bfloat16 g_ql[(size_t)Bn * Nn * Cn];   // q lo
__device__ __nv_bfloat16 g_kh[(size_t)Bn * Nn * Cn];   // k hi  [B, N, C]
__device__ __nv_bfloat16 g_kl[(size_t)Bn * Nn * Cn];   // k lo
__device__ __nv_bfloat16 g_vh[(size_t)Bn * Cn * Nn];   // v hi  [B, C, N]
__device__ __nv_bfloat16 g_vl[(size_t)Bn * Cn * Nn];   // v lo
__device__ float         g_S [(size_t)Bn * Nn * Nn];   // scores fp32
__device__ __nv_bfloat16 g_Ph[(size_t)Bn * Nn * Nn];   // softmax hi [B, N, N]
__device__ __nv_bfloat16 g_Pl[(size_t)Bn * Nn * Nn];   // softmax lo

// ---------------------------------------------------------------------------
// Helpers
// ---------------------------------------------------------------------------
__device__ __forceinline__ uint32_t smem_u32(const void* p) {
    uint32_t a;
    asm("{ .reg .u64 t; cvta.to.shared.u64 t, %1; cvt.u32.u64 %0, t; }"
        : "=r"(a) : "l"(p));
    return a;
}

// SW64 swizzle for 64-byte rows: bits[5:4] ^= bits[8:7]
#define SMEM_SWIZZLE_64B(off) ((off) ^ (((off) >> 3) & 0x30))

__device__ __forceinline__ void ldmx4(uint32_t* r, uint32_t a) {
    asm volatile("ldmatrix.sync.aligned.m8n8.x4.shared.b16 {%0,%1,%2,%3}, [%4];"
        : "=r"(r[0]), "=r"(r[1]), "=r"(r[2]), "=r"(r[3]) : "r"(a));
}

__device__ __forceinline__ void mma16816(float* d, const uint32_t* a,
                                         uint32_t b0, uint32_t b1) {
    asm volatile(
        "mma.sync.aligned.m16n8k16.row.col.f32.bf16.bf16.f32 "
        "{%0,%1,%2,%3}, {%4,%5,%6,%7}, {%8,%9}, {%0,%1,%2,%3};"
        : "+f"(d[0]), "+f"(d[1]), "+f"(d[2]), "+f"(d[3])
        : "r"(a[0]), "r"(a[1]), "r"(a[2]), "r"(a[3]), "r"(b0), "r"(b1));
}

// Copy one 128-row x 32-bf16 tile (64B rows, SW64 swizzle) via cp.async.
// 256 threads -> 2 transfers of 16B each.
__device__ __forceinline__ void cp_tile(uint32_t sdst, const __nv_bfloat16* g,
                                        int rs, int tid) {
    #pragma unroll
    for (int t = 0; t < 2; t++) {
        int u = tid + t * 256;          // 0..511 16B transfers
        int row = u >> 2, q = u & 3;
        uint32_t d = sdst + SMEM_SWIZZLE_64B((uint32_t)(row * 64 + q * 16));
        const void* s = g + (size_t)row * rs + q * 8;
        asm volatile("cp.async.cg.shared.global [%0], [%1], 16;"
                     :: "r"(d), "l"(s));
    }
}

#define CP_COMMIT() asm volatile("cp.async.commit_group;" ::: "memory")
#define CP_WAIT1()  asm volatile("cp.async.wait_group 1;" ::: "memory")
#define CP_WAIT0()  asm volatile("cp.async.wait_group 0;" ::: "memory")

// SMEM: 3 stages x 4 tiles (Ah, Al, Bh, Bl) x 8KB = 96KB
#define TILE_B   8192
#define STAGE_B  (4 * TILE_B)
#define NSTAGES  3
#define MMA_SMEM (NSTAGES * STAGE_B)

// ---------------------------------------------------------------------------
// HMMA mainloop: acc[4][4][4] += A(128xK) @ B(128xK)^T, 2-way bf16 split
// (Ah*Bh + Ah*Bl + Al*Bh), product-major ordering for ILP.
// K in chunks of 32. One __syncthreads per chunk:
//   wait(c) -> barrier -> prefetch(c+2) -> MMA(c)
// The post-wait barrier proves all warps finished MMA(c-1), which protects
// the stage ((c+2)%3 == (c-1)%3) being overwritten by the prefetch.
// 8 warps: warp tile = 64(i) x 32(j); iBase=(wid>>2)*64, jBase=(wid&3)*32.
// ---------------------------------------------------------------------------
__device__ __forceinline__ void mma_mainloop(
    uint32_t sbase,
    const __nv_bfloat16* Ah, const __nv_bfloat16* Al,
    const __nv_bfloat16* Bh, const __nv_bfloat16* Bl,
    int rsA, int rsB, int nch,
    float acc[4][4][4], int tid, int wid, int lane)
{
    const int iBase = (wid >> 2) * 64;
    const int jBase = (wid & 3) * 32;
    const uint32_t lsw  = (uint32_t)(((lane >> 1) & 3) * 16);
    const uint32_t aoff = (uint32_t)((iBase + (lane & 15)) * 64 + (lane >> 4) * 16);
    const uint32_t boff = (uint32_t)((jBase + (lane & 15)) * 64 + (lane >> 4) * 16);

    // Prefetch chunks 0 and 1
    #pragma unroll
    for (int p = 0; p < 2; p++) {
        uint32_t st = sbase + p * STAGE_B;
        int ko = p * 32;
        cp_tile(st + 0 * TILE_B, Ah + ko, rsA, tid);
        cp_tile(st + 1 * TILE_B, Al + ko, rsA, tid);
        cp_tile(st + 2 * TILE_B, Bh + ko, rsB, tid);
        cp_tile(st + 3 * TILE_B, Bl + ko, rsB, tid);
        CP_COMMIT();
    }

    int stage = 0;
    #pragma unroll 1
    for (int c = 0; c < nch; c++) {
        if (c + 1 < nch) CP_WAIT1(); else CP_WAIT0();
        __syncthreads();

        if (c + 2 < nch) {
            int ps = stage + 2; if (ps >= NSTAGES) ps -= NSTAGES;
            uint32_t st = sbase + ps * STAGE_B;
            int ko = (c + 2) * 32;
            cp_tile(st + 0 * TILE_B, Ah + ko, rsA, tid);
            cp_tile(st + 1 * TILE_B, Al + ko, rsA, tid);
            cp_tile(st + 2 * TILE_B, Bh + ko, rsB, tid);
            cp_tile(st + 3 * TILE_B, Bl + ko, rsB, tid);
            CP_COMMIT();
        }

        uint32_t tb = sbase + stage * STAGE_B;
        #pragma unroll
        for (int ks = 0; ks < 2; ks++) {
            uint32_t kb = (uint32_t)(ks * 32);

            uint32_t ah[4][4], al[4][4];
            #pragma unroll
            for (int it = 0; it < 4; it++) {
                uint32_t o = (aoff + it * 1024 + kb) ^ lsw;
                ldmx4(ah[it], tb + o);
                ldmx4(al[it], tb + TILE_B + o);
            }
            uint32_t bh[4][2], bl[4][2];
            #pragma unroll
            for (int jp = 0; jp < 2; jp++) {
                uint32_t o = (boff + jp * 1024 + kb) ^ lsw;
                uint32_t t4[4];
                ldmx4(t4, tb + 2 * TILE_B + o);
                bh[jp * 2][0]     = t4[0]; bh[jp * 2][1]     = t4[2];
                bh[jp * 2 + 1][0] = t4[1]; bh[jp * 2 + 1][1] = t4[3];
                ldmx4(t4, tb + 3 * TILE_B + o);
                bl[jp * 2][0]     = t4[0]; bl[jp * 2][1]     = t4[2];
                bl[jp * 2 + 1][0] = t4[1]; bl[jp * 2 + 1][1] = t4[3];
            }

            // Product-major passes: 16 independent MMAs between acc reuses.
            #pragma unroll
            for (int it = 0; it < 4; it++)
                #pragma unroll
                for (int nt = 0; nt < 4; nt++)
                    mma16816(acc[it][nt], ah[it], bh[nt][0], bh[nt][1]);
            #pragma unroll
            for (int it = 0; it < 4; it++)
                #pragma unroll
                for (int nt = 0; nt < 4; nt++)
                    mma16816(acc[it][nt], ah[it], bl[nt][0], bl[nt][1]);
            #pragma unroll
            for (int it = 0; it < 4; it++)
                #pragma unroll
                for (int nt = 0; nt < 4; nt++)
                    mma16816(acc[it][nt], al[it], bh[nt][0], bh[nt][1]);
        }

        if (++stage == NSTAGES) stage = 0;
    }
}

// ---------------------------------------------------------------------------
// Kernel 1: 1x1 conv projection (SIMT fp32) -> bf16 hi/lo split outputs.
// vmode=0: out [N, C] (q, k).  vmode=1: out [C, N] (v).
// ---------------------------------------------------------------------------
__device__ __forceinline__ void store8_bf16_split(__nv_bfloat16* dh,
                                                  __nv_bfloat16* dl,
                                                  const float* f) {
    uint4 uh, ul;
    __nv_bfloat162* ph = reinterpret_cast<__nv_bfloat162*>(&uh);
    __nv_bfloat162* pl = reinterpret_cast<__nv_bfloat162*>(&ul);
    #pragma unroll
    for (int k = 0; k < 4; k++) {
        float a = f[2 * k], b = f[2 * k + 1];
        __nv_bfloat16 ah = __float2bfloat16_rn(a);
        __nv_bfloat16 bh = __float2bfloat16_rn(b);
        float al = a - __bfloat162float(ah);
        float bl = b - __bfloat162float(bh);
        ph[k] = __halves2bfloat162(ah, bh);
        pl[k] = __halves2bfloat162(__float2bfloat16_rn(al), __float2bfloat16_rn(bl));
    }
    *reinterpret_cast<uint4*>(dh) = uh;
    *reinterpret_cast<uint4*>(dl) = ul;
}

__global__ void __launch_bounds__(256, 2)
proj_kernel(const float* __restrict__ x,
            const float* __restrict__ W,
            const float* __restrict__ bias,
            __nv_bfloat16* __restrict__ oh,
            __nv_bfloat16* __restrict__ ol,
            int vmode) {
    __shared__ __align__(16) float As[16][128];   // As[cc][nn]
    __shared__ __align__(16) float Bs[16][132];   // Bs[cc][oo]

    const int b  = blockIdx.z;
    const int o0 = blockIdx.y * 128;
    const int n0 = blockIdx.x * 128;
    const int tid = threadIdx.x;
    const int tx = tid & 15, ty = tid >> 4;

    const float* xb = x + (size_t)b * Cn * Nn;

    float acc[8][8] = {};

    for (int c0 = 0; c0 < Cn; c0 += 16) {
        #pragma unroll
        for (int k = 0; k < 2; k++) {
            int p = tid + k * 256;
            int cc = p >> 5, nn4 = (p & 31) * 4;
            *reinterpret_cast<float4*>(&As[cc][nn4]) =
                *reinterpret_cast<const float4*>(&xb[(size_t)(c0 + cc) * Nn + n0 + nn4]);
        }
        #pragma unroll
        for (int k = 0; k < 2; k++) {
            int p = tid + k * 256;
            int oo = p >> 2, c4 = (p & 3) * 4;
            float4 w = *reinterpret_cast<const float4*>(&W[(size_t)(o0 + oo) * Cn + c0 + c4]);
            Bs[c4 + 0][oo] = w.x;
            Bs[c4 + 1][oo] = w.y;
            Bs[c4 + 2][oo] = w.z;
            Bs[c4 + 3][oo] = w.w;
        }
        __syncthreads();

        #pragma unroll
        for (int cc = 0; cc < 16; cc++) {
            float4 a0 = *reinterpret_cast<const float4*>(&As[cc][ty * 8]);
            float4 a1 = *reinterpret_cast<const float4*>(&As[cc][ty * 8 + 4]);
            float4 b0 = *reinterpret_cast<const float4*>(&Bs[cc][tx * 8]);
            float4 b1 = *reinterpret_cast<const float4*>(&Bs[cc][tx * 8 + 4]);
            float a[8] = {a0.x, a0.y, a0.z, a0.w, a1.x, a1.y, a1.z, a1.w};
            float bb[8] = {b0.x, b0.y, b0.z, b0.w, b1.x, b1.y, b1.z, b1.w};
            #pragma unroll
            for (int i = 0; i < 8; i++)
                #pragma unroll
                for (int j = 0; j < 8; j++)
                    acc[i][j] += a[i] * bb[j];
        }
        __syncthreads();
    }

    float bj[8];
    #pragma unroll
    for (int j = 0; j < 8; j++) bj[j] = bias[o0 + tx * 8 + j];

    if (!vmode) {
        __nv_bfloat16* dh = oh + (size_t)b * Nn * Cn;
        __nv_bfloat16* dl = ol + (size_t)b * Nn * Cn;
        #pragma unroll
        for (int i = 0; i < 8; i++) {
            float f[8];
            #pragma unroll
            for (int j = 0; j < 8; j++) f[j] = acc[i][j] + bj[j];
            size_t base = (size_t)(n0 + ty * 8 + i) * Cn + o0 + tx * 8;
            store8_bf16_split(dh + base, dl + base, f);
        }
    } else {
        __nv_bfloat16* dh = oh + (size_t)b * Cn * Nn;
        __nv_bfloat16* dl = ol + (size_t)b * Cn * Nn;
        #pragma unroll
        for (int j = 0; j < 8; j++) {
            float f[8];
            #pragma unroll
            for (int i = 0; i < 8; i++) f[i] = acc[i][j] + bj[j];
            size_t base = (size_t)(o0 + tx * 8 + j) * Nn + n0 + ty * 8;
            store8_bf16_split(dh + base, dl + base, f);
        }
    }
}

// ---------------------------------------------------------------------------
// Kernel 2: scores via HMMA.  S[b,i,j] = mask[b,i] * <q_i, k_j>
// ---------------------------------------------------------------------------
__global__ void __launch_bounds__(256, 2)
scores_mma(const float* __restrict__ mask) {
    extern __shared__ char smem[];
    uint32_t sbase = smem_u32(smem);
    const int tid = threadIdx.x;
    const int wid = tid >> 5, lane = tid & 31;

    const int b  = blockIdx.z;
    const int i0 = blockIdx.y * 128;
    const int j0 = blockIdx.x * 128;

    const __nv_bfloat16* Ah = g_qh + ((size_t)b * Nn + i0) * Cn;
    const __nv_bfloat16* Al = g_ql + ((size_t)b * Nn + i0) * Cn;
    const __nv_bfloat16* Bh = g_kh + ((size_t)b * Nn + j0) * Cn;
    const __nv_bfloat16* Bl = g_kl + ((size_t)b * Nn + j0) * Cn;

    float acc[4][4][4] = {};
    mma_mainloop(sbase, Ah, Al, Bh, Bl, Cn, Cn, Cn / 32, acc, tid, wid, lane);

    // Epilogue
    const int iBase = (wid >> 2) * 64;
    const int jBase = (wid & 3) * 32;
    const int g = lane >> 2, cp2 = (lane & 3) * 2;
    const float* mb = mask + (size_t)b * Nn;
    float* Sb = g_S + (size_t)b * Nn * Nn;

    #pragma unroll
    for (int it = 0; it < 4; it++) {
        int r1 = i0 + iBase + it * 16 + g;
        float m1 = mb[r1], m2 = mb[r1 + 8];
        #pragma unroll
        for (int nt = 0; nt < 4; nt++) {
            int cc = j0 + jBase + nt * 8 + cp2;
            float2 v1 = {acc[it][nt][0] * m1, acc[it][nt][1] * m1};
            float2 v2 = {acc[it][nt][2] * m2, acc[it][nt][3] * m2};
            *reinterpret_cast<float2*>(&Sb[(size_t)r1 * Nn + cc])       = v1;
            *reinterpret_cast<float2*>(&Sb[(size_t)(r1 + 8) * Nn + cc]) = v2;
        }
    }
}

// ---------------------------------------------------------------------------
// Kernel 3: row softmax over S; writes P as bf16 hi/lo.
// ---------------------------------------------------------------------------
__global__ void softmax_kernel() {
    const size_t row = blockIdx.x;
    const float* src = g_S + row * Nn;
    __nv_bfloat16* dh = g_Ph + row * Nn;
    __nv_bfloat16* dl = g_Pl + row * Nn;

    const int tid  = threadIdx.x;
    const int warp = tid >> 5;
    const int lane = tid & 31;

    __shared__ float sred[8];
    __shared__ float sbcast;

    float2 v[8];
    float mx = -1e30f;
    #pragma unroll
    for (int t = 0; t < 8; t++) {
        v[t] = *reinterpret_cast<const float2*>(&src[t * 512 + tid * 2]);
        mx = fmaxf(mx, fmaxf(v[t].x, v[t].y));
    }
    #pragma unroll
    for (int o = 16; o > 0; o >>= 1)
        mx = fmaxf(mx, __shfl_xor_sync(0xffffffffu, mx, o));
    if (lane == 0) sred[warp] = mx;
    __syncthreads();
    if (warp == 0) {
        float x = sred[lane & 7];
        #pragma unroll
        for (int o = 4; o > 0; o >>= 1)
            x = fmaxf(x, __shfl_xor_sync(0xffffffffu, x, o));
        if (lane == 0) sbcast = x;
    }
    __syncthreads();
    mx = sbcast;

    float s = 0.f;
    #pragma unroll
    for (int t = 0; t < 8; t++) {
        v[t].x = __expf(v[t].x - mx);
        v[t].y = __expf(v[t].y - mx);
        s += v[t].x + v[t].y;
    }
    #pragma unroll
    for (int o = 16; o > 0; o >>= 1)
        s += __shfl_xor_sync(0xffffffffu, s, o);
    __syncthreads();
    if (lane == 0) sred[warp] = s;
    __syncthreads();
    if (warp == 0) {
        float x = sred[lane & 7];
        #pragma unroll
        for (int o = 4; o > 0; o >>= 1)
            x += __shfl_xor_sync(0xffffffffu, x, o);
        if (lane == 0) sbcast = x;
    }
    __syncthreads();
    const float inv = 1.f / sbcast;

    #pragma unroll
    for (int t = 0; t < 8; t++) {
        float a = v[t].x * inv, b = v[t].y * inv;
        __nv_bfloat16 ah = __float2bfloat16_rn(a);
        __nv_bfloat16 bh = __float2bfloat16_rn(b);
        float al = a - __bfloat162float(ah);
        float bl = b - __bfloat162float(bh);
        int off = t * 512 + tid * 2;
        *reinterpret_cast<__nv_bfloat162*>(&dh[off]) = __halves2bfloat162(ah, bh);
        *reinterpret_cast<__nv_bfloat162*>(&dl[off]) =
            __halves2bfloat162(__float2bfloat16_rn(al), __float2bfloat16_rn(bl));
    }
}

// ---------------------------------------------------------------------------
// Kernel 4: PV via HMMA (computes D^T: rows = c, cols = q) + final blend.
// D[c][q] = sum_j v[c][j] * P[q][j];  out[b,c,q] = queries*m + (1-m)*D
// ---------------------------------------------------------------------------
__global__ void __launch_bounds__(256, 2)
pv_mma(const float* __restrict__ mask,
       const float* __restrict__ queries,
       float* __restrict__ out) {
    extern __shared__ char smem[];
    uint32_t sbase = smem_u32(smem);
    const int tid = threadIdx.x;
    const int wid = tid >> 5, lane = tid & 31;

    const int b  = blockIdx.z;
    const int c0 = blockIdx.y * 128;
    const int q0 = blockIdx.x * 128;

    const __nv_bfloat16* Ah = g_vh + ((size_t)b * Cn + c0) * Nn;
    const __nv_bfloat16* Al = g_vl + ((size_t)b * Cn + c0) * Nn;
    const __nv_bfloat16* Bh = g_Ph + ((size_t)b * Nn + q0) * Nn;
    const __nv_bfloat16* Bl = g_Pl + ((size_t)b * Nn + q0) * Nn;

    float acc[4][4][4] = {};
    mma_mainloop(sbase, Ah, Al, Bh, Bl, Nn, Nn, Nn / 32, acc, tid, wid, lane);

    // Epilogue: rows = c, cols = q (contiguous in output)
    const int iBase = (wid >> 2) * 64;
    const int jBase = (wid & 3) * 32;
    const int g = lane >> 2, cp2 = (lane & 3) * 2;
    const float* mb = mask + (size_t)b * Nn;

    int   qc[4];
    float m0[4], m1[4];
    #pragma unroll
    for (int nt = 0; nt < 4; nt++) {
        qc[nt] = q0 + jBase + nt * 8 + cp2;
        m0[nt] = mb[qc[nt]];
        m1[nt] = mb[qc[nt] + 1];
    }

    #pragma unroll
    for (int it = 0; it < 4; it++) {
        int cr = c0 + iBase + it * 16 + g;
        #pragma unroll
        for (int nt = 0; nt < 4; nt++) {
            size_t gi1 = ((size_t)b * Cn + cr) * Nn + qc[nt];
            size_t gi2 = gi1 + (size_t)8 * Nn;
            float2 qa = *reinterpret_cast<const float2*>(&queries[gi1]);
            float2 qb = *reinterpret_cast<const float2*>(&queries[gi2]);
            float2 o1, o2;
            o1.x = qa.x * m0[nt] + (1.f - m0[nt]) * acc[it][nt][0];
            o1.y = qa.y * m1[nt] + (1.f - m1[nt]) * acc[it][nt][1];
            o2.x = qb.x * m0[nt] + (1.f - m0[nt]) * acc[it][nt][2];
            o2.y = qb.y * m1[nt] + (1.f - m1[nt]) * acc[it][nt][3];
            *reinterpret_cast<float2*>(&out[gi1]) = o1;
            *reinterpret_cast<float2*>(&out[gi2]) = o2;
        }
    }
}

// ---------------------------------------------------------------------------
// Launch
// ---------------------------------------------------------------------------
extern "C" void kernel_launch(void* const* d_in, const int* in_sizes, int n_in,
                              void* d_out, int out_size) {
    const float* queries = (const float*)d_in[0];
    const float* keys    = (const float*)d_in[1];
    const float* mask    = (const float*)d_in[2];
    const float* Wq      = (const float*)d_in[3];
    const float* bq      = (const float*)d_in[4];
    const float* Wk      = (const float*)d_in[5];
    const float* bk      = (const float*)d_in[6];
    const float* Wv      = (const float*)d_in[7];
    const float* bv      = (const float*)d_in[8];
    float* out = (float*)d_out;

    cudaFuncSetAttribute(scores_mma, cudaFuncAttributeMaxDynamicSharedMemorySize,
                         MMA_SMEM);
    cudaFuncSetAttribute(pv_mma, cudaFuncAttributeMaxDynamicSharedMemorySize,
                         MMA_SMEM);

    __nv_bfloat16 *qh, *ql, *kh, *kl, *vh, *vl;
    cudaGetSymbolAddress((void**)&qh, g_qh);
    cudaGetSymbolAddress((void**)&ql, g_ql);
    cudaGetSymbolAddress((void**)&kh, g_kh);
    cudaGetSymbolAddress((void**)&kl, g_kl);
    cudaGetSymbolAddress((void**)&vh, g_vh);
    cudaGetSymbolAddress((void**)&vl, g_vl);

    // Projections (SIMT fp32 -> bf16 hi/lo split outputs)
    dim3 gproj(Nn / 128, Cn / 128, Bn);
    proj_kernel<<<gproj, 256>>>(queries, Wq, bq, qh, ql, 0);
    proj_kernel<<<gproj, 256>>>(keys,    Wk, bk, kh, kl, 0);
    proj_kernel<<<gproj, 256>>>(keys,    Wv, bv, vh, vl, 1);

    // Scores (HMMA, 3-product bf16 split) + mask
    dim3 gsc(Nn / 128, Nn / 128, Bn);
    scores_mma<<<gsc, 256, MMA_SMEM>>>(mask);

    // Row softmax -> P hi/lo
    softmax_kernel<<<Bn * Nn, 256>>>();

    // PV (HMMA, computes D^T) + final blend
    dim3 gpv(Nn / 128, Cn / 128, Bn);
    pv_mma<<<gpv, 256, MMA_SMEM>>>(mask, queries, out);
}

// round 8
// speedup vs baseline: 1.0052x; 1.0017x over previous
#include <cuda_runtime.h>
#include <cuda_bf16.h>
#include <cstdint>
#include <math.h>

// Problem constants
#define Bn 8
#define Cn 256
#define Nn 4096   // 64*64

// ---------------------------------------------------------------------------
// Scratch (device globals; no allocation allowed)
// ---------------------------------------------------------------------------
__device__ __nv_bfloat16 g_qh[(size_t)Bn * Nn * Cn];   // q hi  [B, N, C]
__device__ __nv_bfloat16 g_ql[(size_t)Bn * Nn * Cn];   // q lo
__device__ __nv_bfloat16 g_kh[(size_t)Bn * Nn * Cn];   // k hi  [B, N, C]
__device__ __nv_bfloat16 g_kl[(size_t)Bn * Nn * Cn];   // k lo
__device__ __nv_bfloat16 g_vh[(size_t)Bn * Cn * Nn];   // v hi  [B, C, N]
__device__ __nv_bfloat16 g_vl[(size_t)Bn * Cn * Nn];   // v lo
__device__ float         g_S [(size_t)Bn * Nn * Nn];   // scores fp32
__device__ __nv_bfloat16 g_Ph[(size_t)Bn * Nn * Nn];   // softmax hi [B, N, N]
__device__ __nv_bfloat16 g_Pl[(size_t)Bn * Nn * Nn];   // softmax lo

// ---------------------------------------------------------------------------
// Helpers
// ---------------------------------------------------------------------------
__device__ __forceinline__ uint32_t smem_u32(const void* p) {
    uint32_t a;
    asm("{ .reg .u64 t; cvta.to.shared.u64 t, %1; cvt.u32.u64 %0, t; }"
        : "=r"(a) : "l"(p));
    return a;
}

// SW64 swizzle for 64-byte rows: bits[5:4] ^= bits[8:7]
#define SMEM_SWIZZLE_64B(off) ((off) ^ (((off) >> 3) & 0x30))

__device__ __forceinline__ void ldmx4(uint32_t* r, uint32_t a) {
    asm volatile("ldmatrix.sync.aligned.m8n8.x4.shared.b16 {%0,%1,%2,%3}, [%4];"
        : "=r"(r[0]), "=r"(r[1]), "=r"(r[2]), "=r"(r[3]) : "r"(a));
}

__device__ __forceinline__ void mma16816(float* d, const uint32_t* a,
                                         uint32_t b0, uint32_t b1) {
    asm volatile(
        "mma.sync.aligned.m16n8k16.row.col.f32.bf16.bf16.f32 "
        "{%0,%1,%2,%3}, {%4,%5,%6,%7}, {%8,%9}, {%0,%1,%2,%3};"
        : "+f"(d[0]), "+f"(d[1]), "+f"(d[2]), "+f"(d[3])
        : "r"(a[0]), "r"(a[1]), "r"(a[2]), "r"(a[3]), "r"(b0), "r"(b1));
}

// Copy one 128-row x 32-bf16 tile (64B rows, SW64 swizzle) via cp.async.
// 256 threads -> 2 transfers of 16B each.
__device__ __forceinline__ void cp_tile(uint32_t sdst, const __nv_bfloat16* g,
                                        int rs, int tid) {
    #pragma unroll
    for (int t = 0; t < 2; t++) {
        int u = tid + t * 256;          // 0..511 16B transfers
        int row = u >> 2, q = u & 3;
        uint32_t d = sdst + SMEM_SWIZZLE_64B((uint32_t)(row * 64 + q * 16));
        const void* s = g + (size_t)row * rs + q * 8;
        asm volatile("cp.async.cg.shared.global [%0], [%1], 16;"
                     :: "r"(d), "l"(s));
    }
}

#define CP_COMMIT() asm volatile("cp.async.commit_group;" ::: "memory")
#define CP_WAIT1()  asm volatile("cp.async.wait_group 1;" ::: "memory")
#define CP_WAIT0()  asm volatile("cp.async.wait_group 0;" ::: "memory")

// SMEM: 3 stages x 4 tiles (Ah, Al, Bh, Bl) x 8KB = 96KB
#define TILE_B   8192
#define STAGE_B  (4 * TILE_B)
#define NSTAGES  3
#define MMA_SMEM (NSTAGES * STAGE_B)

// ---------------------------------------------------------------------------
// HMMA mainloop: acc[4][4][4] += A(128xK) @ B(128xK)^T, 2-way bf16 split
// (Ah*Bh + Ah*Bl + Al*Bh), product-major ordering for ILP.
// K in chunks of 32. One __syncthreads per chunk:
//   wait(c) -> barrier -> prefetch(c+2) -> MMA(c)
// The post-wait barrier proves all warps finished MMA(c-1), which protects
// the stage ((c+2)%3 == (c-1)%3) being overwritten by the prefetch.
// 8 warps: warp tile = 64(i) x 32(j); iBase=(wid>>2)*64, jBase=(wid&3)*32.
// ---------------------------------------------------------------------------
__device__ __forceinline__ void mma_mainloop(
    uint32_t sbase,
    const __nv_bfloat16* Ah, const __nv_bfloat16* Al,
    const __nv_bfloat16* Bh, const __nv_bfloat16* Bl,
    int rsA, int rsB, int nch,
    float acc[4][4][4], int tid, int wid, int lane)
{
    const int iBase = (wid >> 2) * 64;
    const int jBase = (wid & 3) * 32;
    const uint32_t lsw  = (uint32_t)(((lane >> 1) & 3) * 16);
    const uint32_t aoff = (uint32_t)((iBase + (lane & 15)) * 64 + (lane >> 4) * 16);
    const uint32_t boff = (uint32_t)((jBase + (lane & 15)) * 64 + (lane >> 4) * 16);

    // Prefetch chunks 0 and 1
    #pragma unroll
    for (int p = 0; p < 2; p++) {
        uint32_t st = sbase + p * STAGE_B;
        int ko = p * 32;
        cp_tile(st + 0 * TILE_B, Ah + ko, rsA, tid);
        cp_tile(st + 1 * TILE_B, Al + ko, rsA, tid);
        cp_tile(st + 2 * TILE_B, Bh + ko, rsB, tid);
        cp_tile(st + 3 * TILE_B, Bl + ko, rsB, tid);
        CP_COMMIT();
    }

    int stage = 0;
    #pragma unroll 1
    for (int c = 0; c < nch; c++) {
        if (c + 1 < nch) CP_WAIT1(); else CP_WAIT0();
        __syncthreads();

        if (c + 2 < nch) {
            int ps = stage + 2; if (ps >= NSTAGES) ps -= NSTAGES;
            uint32_t st = sbase + ps * STAGE_B;
            int ko = (c + 2) * 32;
            cp_tile(st + 0 * TILE_B, Ah + ko, rsA, tid);
            cp_tile(st + 1 * TILE_B, Al + ko, rsA, tid);
            cp_tile(st + 2 * TILE_B, Bh + ko, rsB, tid);
            cp_tile(st + 3 * TILE_B, Bl + ko, rsB, tid);
            CP_COMMIT();
        }

        uint32_t tb = sbase + stage * STAGE_B;
        #pragma unroll
        for (int ks = 0; ks < 2; ks++) {
            uint32_t kb = (uint32_t)(ks * 32);

            uint32_t ah[4][4], al[4][4];
            #pragma unroll
            for (int it = 0; it < 4; it++) {
                uint32_t o = (aoff + it * 1024 + kb) ^ lsw;
                ldmx4(ah[it], tb + o);
                ldmx4(al[it], tb + TILE_B + o);
            }
            uint32_t bh[4][2], bl[4][2];
            #pragma unroll
            for (int jp = 0; jp < 2; jp++) {
                uint32_t o = (boff + jp * 1024 + kb) ^ lsw;
                uint32_t t4[4];
                ldmx4(t4, tb + 2 * TILE_B + o);
                bh[jp * 2][0]     = t4[0]; bh[jp * 2][1]     = t4[2];
                bh[jp * 2 + 1][0] = t4[1]; bh[jp * 2 + 1][1] = t4[3];
                ldmx4(t4, tb + 3 * TILE_B + o);
                bl[jp * 2][0]     = t4[0]; bl[jp * 2][1]     = t4[2];
                bl[jp * 2 + 1][0] = t4[1]; bl[jp * 2 + 1][1] = t4[3];
            }

            // Product-major passes: 16 independent MMAs between acc reuses.
            #pragma unroll
            for (int it = 0; it < 4; it++)
                #pragma unroll
                for (int nt = 0; nt < 4; nt++)
                    mma16816(acc[it][nt], ah[it], bh[nt][0], bh[nt][1]);
            #pragma unroll
            for (int it = 0; it < 4; it++)
                #pragma unroll
                for (int nt = 0; nt < 4; nt++)
                    mma16816(acc[it][nt], ah[it], bl[nt][0], bl[nt][1]);
            #pragma unroll
            for (int it = 0; it < 4; it++)
                #pragma unroll
                for (int nt = 0; nt < 4; nt++)
                    mma16816(acc[it][nt], al[it], bh[nt][0], bh[nt][1]);
        }

        if (++stage == NSTAGES) stage = 0;
    }
}

// ---------------------------------------------------------------------------
// Kernel 1: 1x1 conv projection (SIMT fp32) -> bf16 hi/lo split outputs.
// vmode=0: out [N, C] (q, k).  vmode=1: out [C, N] (v).
// ---------------------------------------------------------------------------
__device__ __forceinline__ void store8_bf16_split(__nv_bfloat16* dh,
                                                  __nv_bfloat16* dl,
                                                  const float* f) {
    uint4 uh, ul;
    __nv_bfloat162* ph = reinterpret_cast<__nv_bfloat162*>(&uh);
    __nv_bfloat162* pl = reinterpret_cast<__nv_bfloat162*>(&ul);
    #pragma unroll
    for (int k = 0; k < 4; k++) {
        float a = f[2 * k], b = f[2 * k + 1];
        __nv_bfloat16 ah = __float2bfloat16_rn(a);
        __nv_bfloat16 bh = __float2bfloat16_rn(b);
        float al = a - __bfloat162float(ah);
        float bl = b - __bfloat162float(bh);
        ph[k] = __halves2bfloat162(ah, bh);
        pl[k] = __halves2bfloat162(__float2bfloat16_rn(al), __float2bfloat16_rn(bl));
    }
    *reinterpret_cast<uint4*>(dh) = uh;
    *reinterpret_cast<uint4*>(dl) = ul;
}

__global__ void __launch_bounds__(256, 2)
proj_kernel(const float* __restrict__ x,
            const float* __restrict__ W,
            const float* __restrict__ bias,
            __nv_bfloat16* __restrict__ oh,
            __nv_bfloat16* __restrict__ ol,
            int vmode) {
    __shared__ __align__(16) float As[16][128];   // As[cc][nn]
    __shared__ __align__(16) float Bs[16][132];   // Bs[cc][oo]

    const int b  = blockIdx.z;
    const int o0 = blockIdx.y * 128;
    const int n0 = blockIdx.x * 128;
    const int tid = threadIdx.x;
    const int tx = tid & 15, ty = tid >> 4;

    const float* xb = x + (size_t)b * Cn * Nn;

    float acc[8][8] = {};

    for (int c0 = 0; c0 < Cn; c0 += 16) {
        #pragma unroll
        for (int k = 0; k < 2; k++) {
            int p = tid + k * 256;
            int cc = p >> 5, nn4 = (p & 31) * 4;
            *reinterpret_cast<float4*>(&As[cc][nn4]) =
                *reinterpret_cast<const float4*>(&xb[(size_t)(c0 + cc) * Nn + n0 + nn4]);
        }
        #pragma unroll
        for (int k = 0; k < 2; k++) {
            int p = tid + k * 256;
            int oo = p >> 2, c4 = (p & 3) * 4;
            float4 w = *reinterpret_cast<const float4*>(&W[(size_t)(o0 + oo) * Cn + c0 + c4]);
            Bs[c4 + 0][oo] = w.x;
            Bs[c4 + 1][oo] = w.y;
            Bs[c4 + 2][oo] = w.z;
            Bs[c4 + 3][oo] = w.w;
        }
        __syncthreads();

        #pragma unroll
        for (int cc = 0; cc < 16; cc++) {
            float4 a0 = *reinterpret_cast<const float4*>(&As[cc][ty * 8]);
            float4 a1 = *reinterpret_cast<const float4*>(&As[cc][ty * 8 + 4]);
            float4 b0 = *reinterpret_cast<const float4*>(&Bs[cc][tx * 8]);
            float4 b1 = *reinterpret_cast<const float4*>(&Bs[cc][tx * 8 + 4]);
            float a[8] = {a0.x, a0.y, a0.z, a0.w, a1.x, a1.y, a1.z, a1.w};
            float bb[8] = {b0.x, b0.y, b0.z, b0.w, b1.x, b1.y, b1.z, b1.w};
            #pragma unroll
            for (int i = 0; i < 8; i++)
                #pragma unroll
                for (int j = 0; j < 8; j++)
                    acc[i][j] += a[i] * bb[j];
        }
        __syncthreads();
    }

    float bj[8];
    #pragma unroll
    for (int j = 0; j < 8; j++) bj[j] = bias[o0 + tx * 8 + j];

    if (!vmode) {
        __nv_bfloat16* dh = oh + (size_t)b * Nn * Cn;
        __nv_bfloat16* dl = ol + (size_t)b * Nn * Cn;
        #pragma unroll
        for (int i = 0; i < 8; i++) {
            float f[8];
            #pragma unroll
            for (int j = 0; j < 8; j++) f[j] = acc[i][j] + bj[j];
            size_t base = (size_t)(n0 + ty * 8 + i) * Cn + o0 + tx * 8;
            store8_bf16_split(dh + base, dl + base, f);
        }
    } else {
        __nv_bfloat16* dh = oh + (size_t)b * Cn * Nn;
        __nv_bfloat16* dl = ol + (size_t)b * Cn * Nn;
        #pragma unroll
        for (int j = 0; j < 8; j++) {
            float f[8];
            #pragma unroll
            for (int i = 0; i < 8; i++) f[i] = acc[i][j] + bj[j];
            size_t base = (size_t)(o0 + tx * 8 + j) * Nn + n0 + ty * 8;
            store8_bf16_split(dh + base, dl + base, f);
        }
    }
}

// ---------------------------------------------------------------------------
// Kernel 2: scores via HMMA.  S[b,i,j] = mask[b,i] * <q_i, k_j>
// ---------------------------------------------------------------------------
__global__ void __launch_bounds__(256, 2)
scores_mma(const float* __restrict__ mask) {
    extern __shared__ char smem[];
    uint32_t sbase = smem_u32(smem);
    const int tid = threadIdx.x;
    const int wid = tid >> 5, lane = tid & 31;

    const int b  = blockIdx.z;
    const int i0 = blockIdx.y * 128;
    const int j0 = blockIdx.x * 128;

    const __nv_bfloat16* Ah = g_qh + ((size_t)b * Nn + i0) * Cn;
    const __nv_bfloat16* Al = g_ql + ((size_t)b * Nn + i0) * Cn;
    const __nv_bfloat16* Bh = g_kh + ((size_t)b * Nn + j0) * Cn;
    const __nv_bfloat16* Bl = g_kl + ((size_t)b * Nn + j0) * Cn;

    float acc[4][4][4] = {};
    mma_mainloop(sbase, Ah, Al, Bh, Bl, Cn, Cn, Cn / 32, acc, tid, wid, lane);

    // Epilogue
    const int iBase = (wid >> 2) * 64;
    const int jBase = (wid & 3) * 32;
    const int g = lane >> 2, cp2 = (lane & 3) * 2;
    const float* mb = mask + (size_t)b * Nn;
    float* Sb = g_S + (size_t)b * Nn * Nn;

    #pragma unroll
    for (int it = 0; it < 4; it++) {
        int r1 = i0 + iBase + it * 16 + g;
        float m1 = mb[r1], m2 = mb[r1 + 8];
        #pragma unroll
        for (int nt = 0; nt < 4; nt++) {
            int cc = j0 + jBase + nt * 8 + cp2;
            float2 v1 = {acc[it][nt][0] * m1, acc[it][nt][1] * m1};
            float2 v2 = {acc[it][nt][2] * m2, acc[it][nt][3] * m2};
            *reinterpret_cast<float2*>(&Sb[(size_t)r1 * Nn + cc])       = v1;
            *reinterpret_cast<float2*>(&Sb[(size_t)(r1 + 8) * Nn + cc]) = v2;
        }
    }
}

// ---------------------------------------------------------------------------
// Kernel 3: row softmax over S; writes P as bf16 hi/lo.
// ---------------------------------------------------------------------------
__global__ void softmax_kernel() {
    const size_t row = blockIdx.x;
    const float* src = g_S + row * Nn;
    __nv_bfloat16* dh = g_Ph + row * Nn;
    __nv_bfloat16* dl = g_Pl + row * Nn;

    const int tid  = threadIdx.x;
    const int warp = tid >> 5;
    const int lane = tid & 31;

    __shared__ float sred[8];
    __shared__ float sbcast;

    float2 v[8];
    float mx = -1e30f;
    #pragma unroll
    for (int t = 0; t < 8; t++) {
        v[t] = *reinterpret_cast<const float2*>(&src[t * 512 + tid * 2]);
        mx = fmaxf(mx, fmaxf(v[t].x, v[t].y));
    }
    #pragma unroll
    for (int o = 16; o > 0; o >>= 1)
        mx = fmaxf(mx, __shfl_xor_sync(0xffffffffu, mx, o));
    if (lane == 0) sred[warp] = mx;
    __syncthreads();
    if (warp == 0) {
        float x = sred[lane & 7];
        #pragma unroll
        for (int o = 4; o > 0; o >>= 1)
            x = fmaxf(x, __shfl_xor_sync(0xffffffffu, x, o));
        if (lane == 0) sbcast = x;
    }
    __syncthreads();
    mx = sbcast;

    float s = 0.f;
    #pragma unroll
    for (int t = 0; t < 8; t++) {
        v[t].x = __expf(v[t].x - mx);
        v[t].y = __expf(v[t].y - mx);
        s += v[t].x + v[t].y;
    }
    #pragma unroll
    for (int o = 16; o > 0; o >>= 1)
        s += __shfl_xor_sync(0xffffffffu, s, o);
    __syncthreads();
    if (lane == 0) sred[warp] = s;
    __syncthreads();
    if (warp == 0) {
        float x = sred[lane & 7];
        #pragma unroll
        for (int o = 4; o > 0; o >>= 1)
            x += __shfl_xor_sync(0xffffffffu, x, o);
        if (lane == 0) sbcast = x;
    }
    __syncthreads();
    const float inv = 1.f / sbcast;

    #pragma unroll
    for (int t = 0; t < 8; t++) {
        float a = v[t].x * inv, b = v[t].y * inv;
        __nv_bfloat16 ah = __float2bfloat16_rn(a);
        __nv_bfloat16 bh = __float2bfloat16_rn(b);
        float al = a - __bfloat162float(ah);
        float bl = b - __bfloat162float(bh);
        int off = t * 512 + tid * 2;
        *reinterpret_cast<__nv_bfloat162*>(&dh[off]) = __halves2bfloat162(ah, bh);
        *reinterpret_cast<__nv_bfloat162*>(&dl[off]) =
            __halves2bfloat162(__float2bfloat16_rn(al), __float2bfloat16_rn(bl));
    }
}

// ---------------------------------------------------------------------------
// Kernel 4: PV via HMMA (computes D^T: rows = c, cols = q) + final blend.
// D[c][q] = sum_j v[c][j] * P[q][j];  out[b,c,q] = queries*m + (1-m)*D
// ---------------------------------------------------------------------------
__global__ void __launch_bounds__(256, 2)
pv_mma(const float* __restrict__ mask,
       const float* __restrict__ queries,
       float* __restrict__ out) {
    extern __shared__ char smem[];
    uint32_t sbase = smem_u32(smem);
    const int tid = threadIdx.x;
    const int wid = tid >> 5, lane = tid & 31;

    const int b  = blockIdx.z;
    const int c0 = blockIdx.y * 128;
    const int q0 = blockIdx.x * 128;

    const __nv_bfloat16* Ah = g_vh + ((size_t)b * Cn + c0) * Nn;
    const __nv_bfloat16* Al = g_vl + ((size_t)b * Cn + c0) * Nn;
    const __nv_bfloat16* Bh = g_Ph + ((size_t)b * Nn + q0) * Nn;
    const __nv_bfloat16* Bl = g_Pl + ((size_t)b * Nn + q0) * Nn;

    float acc[4][4][4] = {};
    mma_mainloop(sbase, Ah, Al, Bh, Bl, Nn, Nn, Nn / 32, acc, tid, wid, lane);

    // Epilogue: rows = c, cols = q (contiguous in output)
    const int iBase = (wid >> 2) * 64;
    const int jBase = (wid & 3) * 32;
    const int g = lane >> 2, cp2 = (lane & 3) * 2;
    const float* mb = mask + (size_t)b * Nn;

    int   qc[4];
    float m0[4], m1[4];
    #pragma unroll
    for (int nt = 0; nt < 4; nt++) {
        qc[nt] = q0 + jBase + nt * 8 + cp2;
        m0[nt] = mb[qc[nt]];
        m1[nt] = mb[qc[nt] + 1];
    }

    #pragma unroll
    for (int it = 0; it < 4; it++) {
        int cr = c0 + iBase + it * 16 + g;
        #pragma unroll
        for (int nt = 0; nt < 4; nt++) {
            size_t gi1 = ((size_t)b * Cn + cr) * Nn + qc[nt];
            size_t gi2 = gi1 + (size_t)8 * Nn;
            float2 qa = *reinterpret_cast<const float2*>(&queries[gi1]);
            float2 qb = *reinterpret_cast<const float2*>(&queries[gi2]);
            float2 o1, o2;
            o1.x = qa.x * m0[nt] + (1.f - m0[nt]) * acc[it][nt][0];
            o1.y = qa.y * m1[nt] + (1.f - m1[nt]) * acc[it][nt][1];
            o2.x = qb.x * m0[nt] + (1.f - m0[nt]) * acc[it][nt][2];
            o2.y = qb.y * m1[nt] + (1.f - m1[nt]) * acc[it][nt][3];
            *reinterpret_cast<float2*>(&out[gi1]) = o1;
            *reinterpret_cast<float2*>(&out[gi2]) = o2;
        }
    }
}

// ---------------------------------------------------------------------------
// Launch
// ---------------------------------------------------------------------------
extern "C" void kernel_launch(void* const* d_in, const int* in_sizes, int n_in,
                              void* d_out, int out_size) {
    const float* queries = (const float*)d_in[0];
    const float* keys    = (const float*)d_in[1];
    const float* mask    = (const float*)d_in[2];
    const float* Wq      = (const float*)d_in[3];
    const float* bq      = (const float*)d_in[4];
    const float* Wk      = (const float*)d_in[5];
    const float* bk      = (const float*)d_in[6];
    const float* Wv      = (const float*)d_in[7];
    const float* bv      = (const float*)d_in[8];
    float* out = (float*)d_out;

    cudaFuncSetAttribute(scores_mma, cudaFuncAttributeMaxDynamicSharedMemorySize,
                         MMA_SMEM);
    cudaFuncSetAttribute(pv_mma, cudaFuncAttributeMaxDynamicSharedMemorySize,
                         MMA_SMEM);

    __nv_bfloat16 *qh, *ql, *kh, *kl, *vh, *vl;
    cudaGetSymbolAddress((void**)&qh, g_qh);
    cudaGetSymbolAddress((void**)&ql, g_ql);
    cudaGetSymbolAddress((void**)&kh, g_kh);
    cudaGetSymbolAddress((void**)&kl, g_kl);
    cudaGetSymbolAddress((void**)&vh, g_vh);
    cudaGetSymbolAddress((void**)&vl, g_vl);

    // Projections (SIMT fp32 -> bf16 hi/lo split outputs)
    dim3 gproj(Nn / 128, Cn / 128, Bn);
    proj_kernel<<<gproj, 256>>>(queries, Wq, bq, qh, ql, 0);
    proj_kernel<<<gproj, 256>>>(keys,    Wk, bk, kh, kl, 0);
    proj_kernel<<<gproj, 256>>>(keys,    Wv, bv, vh, vl, 1);

    // Scores (HMMA, 3-product bf16 split) + mask
    dim3 gsc(Nn / 128, Nn / 128, Bn);
    scores_mma<<<gsc, 256, MMA_SMEM>>>(mask);

    // Row softmax -> P hi/lo
    softmax_kernel<<<Bn * Nn, 256>>>();

    // PV (HMMA, computes D^T) + final blend
    dim3 gpv(Nn / 128, Cn / 128, Bn);
    pv_mma<<<gpv, 256, MMA_SMEM>>>(mask, queries, out);
}